// round 11
// baseline (speedup 1.0000x reference)
#include <cuda_runtime.h>
#include <cuda_fp16.h>

// 2-layer GCN, N=100000, E=3200000, 25->16->2, log_softmax.
// out_l[i] = dinv[i]*(sum_{j->i} g[j] + g[i]) + b,  g = dinv * (x @ W).
// Bucketed CSR (CAP slots/node, no prefix scan; fill doubles as degree pass;
// overflow spill list keeps exactness). Gathers: fp32 accumulation, fused
// epilogues; layer-1 payload fp16 (32B). Index loads vectorized int4 to cut
// L1 wavefronts 4x on the index side. edge_index is int32 on device.

#define NMAX   100000
#define CAP    128
#define F_IN   25
#define F_HID  16
#define F_OUT  2
#define SPILLMAX 8192

struct __align__(16) H8 { __half2 h[4]; };   // 8 halfs = 16B

// ---- scratch (device globals; no allocation allowed) ----
__device__ int   d_cnt [NMAX];            // degree counters (= deg after fill)
__device__ int   d_srcb[NMAX * CAP];      // bucketed CSR: sources per target
__device__ int   d_spill_n;
__device__ int   d_spill[2 * SPILLMAX];   // (target, source) overflow pairs
__device__ float d_dinv[NMAX];
__device__ H8    d_g1h [NMAX * 2];        // 16 halfs per node (32B)
__device__ float d_g2  [NMAX * F_OUT];

// ---- kernels ----

__global__ void k_zero(int n) {
    int i = blockIdx.x * blockDim.x + threadIdx.x;
    if (i < n) d_cnt[i] = 0;
    if (i == 0) d_spill_n = 0;
}

// Fill bucketed CSR; 4 edges per thread via int4 (more atomics in flight).
__global__ void k_fill(const int* __restrict__ row,
                       const int* __restrict__ col, int n_edges, int n_nodes) {
    int i = blockIdx.x * blockDim.x + threadIdx.x;
    int base = i * 4;
    if (base >= n_edges) return;
    if (base + 3 < n_edges) {
        int4 rv = __ldg(reinterpret_cast<const int4*>(row + base));
        int4 tv = __ldg(reinterpret_cast<const int4*>(col + base));
        int rr[4] = {rv.x, rv.y, rv.z, rv.w};
        int tt[4] = {tv.x, tv.y, tv.z, tv.w};
#pragma unroll
        for (int q = 0; q < 4; q++) {
            unsigned r = (unsigned)rr[q], t = (unsigned)tt[q];
            if (r < (unsigned)n_nodes && t < (unsigned)n_nodes) {
                int slot = atomicAdd(&d_cnt[t], 1);
                if (slot < CAP) {
                    d_srcb[t * CAP + slot] = (int)r;
                } else {
                    int s = atomicAdd(&d_spill_n, 1);
                    if (s < SPILLMAX) {
                        d_spill[2 * s + 0] = (int)t;
                        d_spill[2 * s + 1] = (int)r;
                    }
                }
            }
        }
    } else {
        for (int e = base; e < n_edges; e++) {
            unsigned r = (unsigned)__ldg(&row[e]);
            unsigned t = (unsigned)__ldg(&col[e]);
            if (r < (unsigned)n_nodes && t < (unsigned)n_nodes) {
                int slot = atomicAdd(&d_cnt[t], 1);
                if (slot < CAP) {
                    d_srcb[t * CAP + slot] = (int)r;
                } else {
                    int s = atomicAdd(&d_spill_n, 1);
                    if (s < SPILLMAX) {
                        d_spill[2 * s + 0] = (int)t;
                        d_spill[2 * s + 1] = (int)r;
                    }
                }
            }
        }
    }
}

// dinv = rsqrt(deg_in + 1);  g1 = dinv * (x @ W1), stored fp16-packed.
__global__ void k_node1(const float* __restrict__ x,
                        const float* __restrict__ W1, int n) {
    __shared__ float sW[F_IN * F_HID];
    for (int i = threadIdx.x; i < F_IN * F_HID; i += blockDim.x)
        sW[i] = W1[i];
    __syncthreads();

    int i = blockIdx.x * blockDim.x + threadIdx.x;
    if (i >= n) return;

    float xv[F_IN];
#pragma unroll
    for (int k = 0; k < F_IN; k++) xv[k] = x[i * F_IN + k];

    float dinv = rsqrtf((float)(d_cnt[i] + 1));
    d_dinv[i] = dinv;

    float s[F_HID];
#pragma unroll
    for (int f = 0; f < F_HID; f++) {
        float acc = 0.0f;
#pragma unroll
        for (int k = 0; k < F_IN; k++) acc += xv[k] * sW[k * F_HID + f];
        s[f] = dinv * acc;
    }
#pragma unroll
    for (int c = 0; c < 2; c++) {
        H8 o;
#pragma unroll
        for (int k = 0; k < 4; k++)
            o.h[k] = __floats2half2_rn(s[c * 8 + 2 * k], s[c * 8 + 2 * k + 1]);
        d_g1h[i * 2 + c] = o;
    }
}

// Gather layer 1 + epilogue-1 + layer-2 transform, fused.
// 2 lanes per node; lane c owns features [8c, 8c+8). The lane pair's two 16B
// loads of a neighbor coalesce into one 32B sector. Indices loaded as int4
// (base is 512B-aligned, k multiple of 4). fp32 accumulation.
__global__ void k_gather1(const float* __restrict__ b1,
                          const float* __restrict__ W2, int n) {
    int gid = blockIdx.x * blockDim.x + threadIdx.x;
    int i = gid >> 1;
    int c = gid & 1;
    bool valid = (i < n);
    int ic = valid ? i : (n - 1);   // clamp: keep lane pair active for shfl

    int cnt = d_cnt[ic];
    int deg = min(cnt, CAP);
    int base = ic * CAP;
    float dinv = d_dinv[ic];

    float a[8];
    {
        H8 v = d_g1h[ic * 2 + c];    // self term
#pragma unroll
        for (int k = 0; k < 4; k++) {
            float2 f = __half22float2(v.h[k]);
            a[2 * k] = f.x; a[2 * k + 1] = f.y;
        }
    }

    int k = 0;
    for (; k + 4 <= deg; k += 4) {
        int4 jv = __ldg(reinterpret_cast<const int4*>(&d_srcb[base + k]));
        H8 v0 = d_g1h[jv.x * 2 + c];
        H8 v1 = d_g1h[jv.y * 2 + c];
        H8 v2 = d_g1h[jv.z * 2 + c];
        H8 v3 = d_g1h[jv.w * 2 + c];
#pragma unroll
        for (int q = 0; q < 4; q++) {
            float2 f0 = __half22float2(v0.h[q]);
            float2 f1 = __half22float2(v1.h[q]);
            float2 f2 = __half22float2(v2.h[q]);
            float2 f3 = __half22float2(v3.h[q]);
            a[2 * q]     += (f0.x + f1.x) + (f2.x + f3.x);
            a[2 * q + 1] += (f0.y + f1.y) + (f2.y + f3.y);
        }
    }
    for (; k < deg; k++) {
        int j = __ldg(&d_srcb[base + k]);
        H8 v = d_g1h[j * 2 + c];
#pragma unroll
        for (int q = 0; q < 4; q++) {
            float2 f = __half22float2(v.h[q]);
            a[2 * q] += f.x; a[2 * q + 1] += f.y;
        }
    }

    // overflow path (expected never taken): scan spill list for this target
    if (cnt > CAP) {
        int ns = min(d_spill_n, SPILLMAX);
        for (int s = 0; s < ns; s++) {
            if (d_spill[2 * s] == ic) {
                int j = d_spill[2 * s + 1];
                H8 v = d_g1h[j * 2 + c];
#pragma unroll
                for (int q = 0; q < 4; q++) {
                    float2 f = __half22float2(v.h[q]);
                    a[2 * q] += f.x; a[2 * q + 1] += f.y;
                }
            }
        }
    }

    // epilogue-1: relu(dinv*a + b1), partial dot into W2
    float h0 = 0.0f, h1 = 0.0f;
#pragma unroll
    for (int f = 0; f < 8; f++) {
        int fg = c * 8 + f;
        float tt = fmaxf(dinv * a[f] + __ldg(&b1[fg]), 0.0f);
        h0 += tt * __ldg(&W2[fg * F_OUT + 0]);
        h1 += tt * __ldg(&W2[fg * F_OUT + 1]);
    }
    h0 += __shfl_xor_sync(0xffffffffu, h0, 1);
    h1 += __shfl_xor_sync(0xffffffffu, h1, 1);

    if (valid && c == 0) {
        d_g2[i * 2 + 0] = dinv * h0;
        d_g2[i * 2 + 1] = dinv * h1;
    }
}

// Gather layer 2 + epilogue-2 + log_softmax, fused. 1 thread per node.
// Indices loaded as int4 pairs.
__global__ void k_gather2(const float* __restrict__ b2,
                          float* __restrict__ out, int n) {
    int i = blockIdx.x * blockDim.x + threadIdx.x;
    if (i >= n) return;

    int cnt = d_cnt[i];
    int deg = min(cnt, CAP);
    int base = i * CAP;
    float dinv = d_dinv[i];

    float2 acc = *reinterpret_cast<const float2*>(&d_g2[i * 2]);

    int k = 0;
    for (; k + 8 <= deg; k += 8) {
        int4 ja = __ldg(reinterpret_cast<const int4*>(&d_srcb[base + k]));
        int4 jb = __ldg(reinterpret_cast<const int4*>(&d_srcb[base + k + 4]));
        int jj[8] = {ja.x, ja.y, ja.z, ja.w, jb.x, jb.y, jb.z, jb.w};
#pragma unroll
        for (int q = 0; q < 8; q++) {
            float2 v = *reinterpret_cast<const float2*>(&d_g2[jj[q] * 2]);
            acc.x += v.x; acc.y += v.y;
        }
    }
    for (; k < deg; k++) {
        int j = __ldg(&d_srcb[base + k]);
        float2 v = *reinterpret_cast<const float2*>(&d_g2[j * 2]);
        acc.x += v.x; acc.y += v.y;
    }

    if (cnt > CAP) {
        int ns = min(d_spill_n, SPILLMAX);
        for (int s = 0; s < ns; s++) {
            if (d_spill[2 * s] == i) {
                int j = d_spill[2 * s + 1];
                float2 v = *reinterpret_cast<const float2*>(&d_g2[j * 2]);
                acc.x += v.x; acc.y += v.y;
            }
        }
    }

    float z0 = dinv * acc.x + __ldg(&b2[0]);
    float z1 = dinv * acc.y + __ldg(&b2[1]);
    float m = fmaxf(z0, z1);
    float lse = m + logf(expf(z0 - m) + expf(z1 - m));
    out[i * 2 + 0] = z0 - lse;
    out[i * 2 + 1] = z1 - lse;
}

// ---- launch ----

extern "C" void kernel_launch(void* const* d_in, const int* in_sizes, int n_in,
                              void* d_out, int out_size) {
    const float* x  = (const float*)d_in[0];
    const int*   ei = (const int*)d_in[1];
    const float* W1 = (const float*)d_in[2];
    const float* b1 = (const float*)d_in[3];
    const float* W2 = (const float*)d_in[4];
    const float* b2 = (const float*)d_in[5];
    float*       out = (float*)d_out;

    int n_nodes = in_sizes[0] / F_IN;
    int n_edges = in_sizes[1] / 2;
    const int* row = ei;             // sources
    const int* col = ei + n_edges;   // targets

    const int B = 256;
    int gn  = (n_nodes + B - 1) / B;
    int ge4 = (((n_edges + 3) / 4) + B - 1) / B;
    int gn2 = (int)((2LL * n_nodes + B - 1) / B);

    k_zero   <<<gn, B>>>(n_nodes);
    k_fill   <<<ge4, B>>>(row, col, n_edges, n_nodes);
    k_node1  <<<gn, B>>>(x, W1, n_nodes);
    k_gather1<<<gn2, B>>>(b1, W2, n_nodes);
    k_gather2<<<gn, B>>>(b2, out, n_nodes);
}

// round 13
// speedup vs baseline: 1.4295x; 1.4295x over previous
#include <cuda_runtime.h>
#include <cuda_fp16.h>

// 2-layer GCN, N=100000, E=3200000, 25->16->2, log_softmax.
// out_l[i] = dinv[i]*(sum_{j->i} g[j] + g[i]) + b,  g = dinv * (x @ W).
// Bucketed CSR with TRANSPOSED (column-major) buckets: slot k of node i lives
// at d_srcb[k*NMAX + i], so index loads in the gathers coalesce across the
// warp (2 sectors per k instead of 16). Fill doubles as the degree pass;
// overflow spill list keeps exactness. Gathers: fp32 accumulation, fused
// epilogues; layer-1 payload fp16 (32B/node). edge_index is int32 on device.

#define NMAX   100000
#define CAP    128
#define F_IN   25
#define F_HID  16
#define F_OUT  2
#define SPILLMAX 8192

struct __align__(16) H8 { __half2 h[4]; };   // 8 halfs = 16B

// ---- scratch (device globals; no allocation allowed) ----
__device__ int   d_cnt [NMAX];            // degree counters (= deg after fill)
__device__ int   d_srcb[CAP * NMAX];      // transposed buckets: [slot][node]
__device__ int   d_spill_n;
__device__ int   d_spill[2 * SPILLMAX];   // (target, source) overflow pairs
__device__ float d_dinv[NMAX];
__device__ H8    d_g1h [NMAX * 2];        // 16 halfs per node (32B)
__device__ float d_g2  [NMAX * F_OUT];

// ---- kernels ----

__global__ void k_zero(int n) {
    int i = blockIdx.x * blockDim.x + threadIdx.x;
    if (i < n) d_cnt[i] = 0;
    if (i == 0) d_spill_n = 0;
}

// Fill bucketed CSR; counters double as degree histogram.
__global__ void k_fill(const int* __restrict__ row,
                       const int* __restrict__ col, int n_edges, int n_nodes) {
    int e = blockIdx.x * blockDim.x + threadIdx.x;
    if (e >= n_edges) return;
    unsigned r = (unsigned)__ldg(&row[e]);
    unsigned t = (unsigned)__ldg(&col[e]);
    if (r >= (unsigned)n_nodes || t >= (unsigned)n_nodes) return;
    int slot = atomicAdd(&d_cnt[t], 1);
    if (slot < CAP) {
        d_srcb[slot * NMAX + t] = (int)r;
    } else {
        int s = atomicAdd(&d_spill_n, 1);
        if (s < SPILLMAX) {
            d_spill[2 * s + 0] = (int)t;
            d_spill[2 * s + 1] = (int)r;
        }
    }
}

// dinv = rsqrt(deg_in + 1);  g1 = dinv * (x @ W1), stored fp16-packed.
__global__ void k_node1(const float* __restrict__ x,
                        const float* __restrict__ W1, int n) {
    __shared__ float sW[F_IN * F_HID];
    for (int i = threadIdx.x; i < F_IN * F_HID; i += blockDim.x)
        sW[i] = W1[i];
    __syncthreads();

    int i = blockIdx.x * blockDim.x + threadIdx.x;
    if (i >= n) return;

    float xv[F_IN];
#pragma unroll
    for (int k = 0; k < F_IN; k++) xv[k] = x[i * F_IN + k];

    float dinv = rsqrtf((float)(d_cnt[i] + 1));
    d_dinv[i] = dinv;

    float s[F_HID];
#pragma unroll
    for (int f = 0; f < F_HID; f++) {
        float acc = 0.0f;
#pragma unroll
        for (int k = 0; k < F_IN; k++) acc += xv[k] * sW[k * F_HID + f];
        s[f] = dinv * acc;
    }
#pragma unroll
    for (int c = 0; c < 2; c++) {
        H8 o;
#pragma unroll
        for (int k = 0; k < 4; k++)
            o.h[k] = __floats2half2_rn(s[c * 8 + 2 * k], s[c * 8 + 2 * k + 1]);
        d_g1h[i * 2 + c] = o;
    }
}

// Gather layer 1 + epilogue-1 + layer-2 transform, fused.
// 2 lanes per node; lane c owns features [8c, 8c+8). The lane pair's two 16B
// payload loads coalesce to one 32B sector. Index loads coalesce across the
// warp (16 consecutive nodes per k). fp32 accumulation.
__global__ void k_gather1(const float* __restrict__ b1,
                          const float* __restrict__ W2, int n) {
    int gid = blockIdx.x * blockDim.x + threadIdx.x;
    int i = gid >> 1;
    int c = gid & 1;
    bool valid = (i < n);
    int ic = valid ? i : (n - 1);   // clamp: keep lane pair active for shfl

    int cnt = d_cnt[ic];
    int deg = min(cnt, CAP);
    float dinv = d_dinv[ic];

    float a[8];
    {
        H8 v = d_g1h[ic * 2 + c];    // self term
#pragma unroll
        for (int k = 0; k < 4; k++) {
            float2 f = __half22float2(v.h[k]);
            a[2 * k] = f.x; a[2 * k + 1] = f.y;
        }
    }

    int k = 0;
    for (; k + 4 <= deg; k += 4) {
        int j0 = __ldg(&d_srcb[(k + 0) * NMAX + ic]);
        int j1 = __ldg(&d_srcb[(k + 1) * NMAX + ic]);
        int j2 = __ldg(&d_srcb[(k + 2) * NMAX + ic]);
        int j3 = __ldg(&d_srcb[(k + 3) * NMAX + ic]);
        H8 v0 = d_g1h[j0 * 2 + c];
        H8 v1 = d_g1h[j1 * 2 + c];
        H8 v2 = d_g1h[j2 * 2 + c];
        H8 v3 = d_g1h[j3 * 2 + c];
#pragma unroll
        for (int q = 0; q < 4; q++) {
            float2 f0 = __half22float2(v0.h[q]);
            float2 f1 = __half22float2(v1.h[q]);
            float2 f2 = __half22float2(v2.h[q]);
            float2 f3 = __half22float2(v3.h[q]);
            a[2 * q]     += (f0.x + f1.x) + (f2.x + f3.x);
            a[2 * q + 1] += (f0.y + f1.y) + (f2.y + f3.y);
        }
    }
    for (; k < deg; k++) {
        int j = __ldg(&d_srcb[k * NMAX + ic]);
        H8 v = d_g1h[j * 2 + c];
#pragma unroll
        for (int q = 0; q < 4; q++) {
            float2 f = __half22float2(v.h[q]);
            a[2 * q] += f.x; a[2 * q + 1] += f.y;
        }
    }

    // overflow path (expected never taken): scan spill list for this target
    if (cnt > CAP) {
        int ns = min(d_spill_n, SPILLMAX);
        for (int s = 0; s < ns; s++) {
            if (d_spill[2 * s] == ic) {
                int j = d_spill[2 * s + 1];
                H8 v = d_g1h[j * 2 + c];
#pragma unroll
                for (int q = 0; q < 4; q++) {
                    float2 f = __half22float2(v.h[q]);
                    a[2 * q] += f.x; a[2 * q + 1] += f.y;
                }
            }
        }
    }

    // epilogue-1: relu(dinv*a + b1), partial dot into W2
    float h0 = 0.0f, h1 = 0.0f;
#pragma unroll
    for (int f = 0; f < 8; f++) {
        int fg = c * 8 + f;
        float tt = fmaxf(dinv * a[f] + __ldg(&b1[fg]), 0.0f);
        h0 += tt * __ldg(&W2[fg * F_OUT + 0]);
        h1 += tt * __ldg(&W2[fg * F_OUT + 1]);
    }
    h0 += __shfl_xor_sync(0xffffffffu, h0, 1);
    h1 += __shfl_xor_sync(0xffffffffu, h1, 1);

    if (valid && c == 0) {
        d_g2[i * 2 + 0] = dinv * h0;
        d_g2[i * 2 + 1] = dinv * h1;
    }
}

// Gather layer 2 + epilogue-2 + log_softmax, fused. 1 thread per node.
// Index loads coalesce across the warp (32 consecutive nodes per k).
__global__ void k_gather2(const float* __restrict__ b2,
                          float* __restrict__ out, int n) {
    int i = blockIdx.x * blockDim.x + threadIdx.x;
    if (i >= n) return;

    int cnt = d_cnt[i];
    int deg = min(cnt, CAP);
    float dinv = d_dinv[i];

    float2 acc = *reinterpret_cast<const float2*>(&d_g2[i * 2]);

    int k = 0;
    for (; k + 8 <= deg; k += 8) {
        int jj[8];
#pragma unroll
        for (int q = 0; q < 8; q++) jj[q] = __ldg(&d_srcb[(k + q) * NMAX + i]);
#pragma unroll
        for (int q = 0; q < 8; q++) {
            float2 v = *reinterpret_cast<const float2*>(&d_g2[jj[q] * 2]);
            acc.x += v.x; acc.y += v.y;
        }
    }
    for (; k < deg; k++) {
        int j = __ldg(&d_srcb[k * NMAX + i]);
        float2 v = *reinterpret_cast<const float2*>(&d_g2[j * 2]);
        acc.x += v.x; acc.y += v.y;
    }

    if (cnt > CAP) {
        int ns = min(d_spill_n, SPILLMAX);
        for (int s = 0; s < ns; s++) {
            if (d_spill[2 * s] == i) {
                int j = d_spill[2 * s + 1];
                float2 v = *reinterpret_cast<const float2*>(&d_g2[j * 2]);
                acc.x += v.x; acc.y += v.y;
            }
        }
    }

    float z0 = dinv * acc.x + __ldg(&b2[0]);
    float z1 = dinv * acc.y + __ldg(&b2[1]);
    float m = fmaxf(z0, z1);
    float lse = m + logf(expf(z0 - m) + expf(z1 - m));
    out[i * 2 + 0] = z0 - lse;
    out[i * 2 + 1] = z1 - lse;
}

// ---- launch ----

extern "C" void kernel_launch(void* const* d_in, const int* in_sizes, int n_in,
                              void* d_out, int out_size) {
    const float* x  = (const float*)d_in[0];
    const int*   ei = (const int*)d_in[1];
    const float* W1 = (const float*)d_in[2];
    const float* b1 = (const float*)d_in[3];
    const float* W2 = (const float*)d_in[4];
    const float* b2 = (const float*)d_in[5];
    float*       out = (float*)d_out;

    int n_nodes = in_sizes[0] / F_IN;
    int n_edges = in_sizes[1] / 2;
    const int* row = ei;             // sources
    const int* col = ei + n_edges;   // targets

    const int B = 256;
    int gn  = (n_nodes + B - 1) / B;
    int ge  = (n_edges + B - 1) / B;
    int gn2 = (int)((2LL * n_nodes + B - 1) / B);

    k_zero   <<<gn, B>>>(n_nodes);
    k_fill   <<<ge, B>>>(row, col, n_edges, n_nodes);
    k_node1  <<<gn, B>>>(x, W1, n_nodes);
    k_gather1<<<gn2, B>>>(b1, W2, n_nodes);
    k_gather2<<<gn, B>>>(b2, out, n_nodes);
}